// round 16
// baseline (speedup 1.0000x reference)
#include <cuda_runtime.h>

#define QSCALE 0.17677669529663687f  // 1/sqrt(32)

// pack two fp32 -> half2 bits (lo = first/lower k index)
__device__ __forceinline__ unsigned h2pack(float lo, float hi) {
    unsigned u;
    asm("cvt.rn.f16x2.f32 %0, %1, %2;" : "=r"(u) : "f"(hi), "f"(lo));
    return u;
}
// pair permutation within an 8-pair slab
__device__ __forceinline__ int PI8(int s) { return ((s & 3) << 1) | ((s >> 2) & 1); }
__device__ __forceinline__ int pcperm(int p) { return (p & ~7) | PI8(p & 7); }

__device__ __forceinline__ uint2 ldu2(const unsigned* p) { return *(const uint2*)p; }

__device__ __forceinline__ void pbar(int id) {
    asm volatile("bar.sync %0, 64;" :: "r"(id) : "memory");
}
__device__ __forceinline__ void bbar(int id) {
    asm volatile("bar.sync %0, 256;" :: "r"(id) : "memory");
}

__device__ __forceinline__ void mma16(float* c,
    unsigned a0, unsigned a1, unsigned a2, unsigned a3,
    unsigned b0, unsigned b1)
{
    asm volatile(
        "mma.sync.aligned.m16n8k16.row.col.f32.f16.f16.f32 "
        "{%0,%1,%2,%3}, {%4,%5,%6,%7}, {%8,%9}, {%0,%1,%2,%3};"
        : "+f"(c[0]), "+f"(c[1]), "+f"(c[2]), "+f"(c[3])
        : "r"(a0), "r"(a1), "r"(a2), "r"(a3), "r"(b0), "r"(b1));
}

// ---------------------------------------------------------------------------
// Temporal: ONE CTA per (b, f-pair). 128 rows = two 64-row t-blocks.
// All-head weights staged once; X fragments cached in registers; no full
// syncthreads inside the head loop (block barriers only).
// smem words: Xs@0[128][40] Kh@5120[128][24] Vt@8192[32][72] Qh@10496[128][24]
//  Ps@13568[128][40] Oh@18688[128][24] WBall@21760(15360) WoSall@37120(6144)
//  Bs@43264(448) ExM@43712(256) ExS@43968(256)  total 44224 w = 176896 B
// ---------------------------------------------------------------------------
__global__ void __launch_bounds__(512) temporal_kernel(
    const float* __restrict__ x,
    const float* __restrict__ wq, const float* __restrict__ bq,
    const float* __restrict__ wk, const float* __restrict__ bk,
    const float* __restrict__ wv, const float* __restrict__ bv,
    const float* __restrict__ wo, const float* __restrict__ bo,
    float* __restrict__ out)
{
    extern __shared__ float sm[];
    unsigned* Xs     = (unsigned*)sm;
    unsigned* Kh     = (unsigned*)sm + 5120;
    unsigned* Vt     = (unsigned*)sm + 8192;
    unsigned* Qh     = (unsigned*)sm + 10496;
    unsigned* Ps     = (unsigned*)sm + 13568;
    unsigned* Oh     = (unsigned*)sm + 18688;
    unsigned* WBall  = (unsigned*)sm + 21760;
    unsigned* WoSall = (unsigned*)sm + 37120;
    float*    Bs     = sm + 43264;
    float*    ExM    = sm + 43712;
    float*    ExS    = sm + 43968;

    const int tid  = threadIdx.x;
    const int lane = tid & 31, warp = tid >> 5;
    const int g = lane >> 2, t4 = lane & 3;
    const int b = blockIdx.x >> 6, fp = blockIdx.x & 63;

    {
        const float4* x4 = (const float4*)x;
        for (int i = tid; i < 2048; i += 512) {
            int row = i >> 4, c = i & 15;
            int fb = row >> 6, t = row & 63;
            int f = fp * 2 + fb;
            float4 v = x4[(((b * 64 + t) * 128 + f) << 4) + c];
            Xs[row * 40 + pcperm(2 * c)]     = h2pack(v.x, v.y);
            Xs[row * 40 + pcperm(2 * c + 1)] = h2pack(v.z, v.w);
        }
    }
    // stage ALL heads' weights once: WBall[(m*4+h)*1280 + n*40 + perm(p)]
    for (int i = tid; i < 12288; i += 512) {
        int mh = i >> 10;               // m*4 + h
        int m = mh >> 2, hh = mh & 3;
        int r = i & 1023;
        int n = r >> 5, p = r & 31;
        const float* w = (m == 0) ? wq : (m == 1) ? wk : wv;
        WBall[mh * 1280 + n * 40 + pcperm(p)] =
            h2pack(w[(2 * p) * 128 + hh * 32 + n],
                   w[(2 * p + 1) * 128 + hh * 32 + n]);
    }
    for (int i = tid; i < 4096; i += 512) {
        int hh = i >> 10, r = i & 1023;
        int d = r >> 4, p = r & 15;
        WoSall[hh * 1536 + d * 24 + ((p & 8) | PI8(p & 7))] =
            h2pack(wo[(hh * 32 + 2 * p) * 64 + d],
                   wo[(hh * 32 + 2 * p + 1) * 64 + d]);
    }
    if (tid < 448) {
        float v;
        if      (tid < 128) v = bq[tid];
        else if (tid < 256) v = bk[tid - 128];
        else if (tid < 384) v = bv[tid - 256];
        else                v = bo[tid - 384];
        Bs[tid] = v;
    }
    __syncthreads();

    const int mt8 = warp & 7, nh2 = warp >> 3;
    const int r0 = mt8 * 16 + g, r1 = r0 + 8;
    const int blk = mt8 >> 2;
    const int pid = 8 + mt8;
    const int bid = 1 + blk;

    // X A-fragments cached in registers (head-invariant)
    uint2 xa0[4], xa1[4];
    #pragma unroll
    for (int kt = 0; kt < 4; kt++) {
        int ko = kt * 8 + 2 * t4;
        xa0[kt] = ldu2(Xs + r0 * 40 + ko);
        xa1[kt] = ldu2(Xs + r1 * 40 + ko);
    }

    float pacc[4][4] = {};

    for (int h = 0; h < 4; h++) {
        const int hb = h * 32;
        const unsigned* Wq_h  = WBall + h * 1280;
        const unsigned* Wk_h  = WBall + (4 + h) * 1280;
        const unsigned* Wv_h  = WBall + (8 + h) * 1280;
        const unsigned* WoS_h = WoSall + h * 1536;
        bbar(bid);   // prev head's Kh/Vt readers (block-local) done

        // fused Q/K/V projections: M=128 N=32 K=64
        {
            float aQ[2][4], aK[2][4], aV[2][4];
            #pragma unroll
            for (int nt = 0; nt < 2; nt++) {
                int c0 = nh2 * 16 + nt * 8 + 2 * t4;
                aQ[nt][0] = Bs[hb + c0];       aQ[nt][1] = Bs[hb + c0 + 1];
                aQ[nt][2] = aQ[nt][0];         aQ[nt][3] = aQ[nt][1];
                aK[nt][0] = Bs[128 + hb + c0]; aK[nt][1] = Bs[128 + hb + c0 + 1];
                aK[nt][2] = aK[nt][0];         aK[nt][3] = aK[nt][1];
                aV[nt][0] = Bs[256 + hb + c0]; aV[nt][1] = Bs[256 + hb + c0 + 1];
                aV[nt][2] = aV[nt][0];         aV[nt][3] = aV[nt][1];
            }
            #pragma unroll
            for (int kt = 0; kt < 4; kt++) {
                int ko = kt * 8 + 2 * t4;
                #pragma unroll
                for (int nt = 0; nt < 2; nt++) {
                    int n0 = nh2 * 16 + nt * 8 + g;
                    uint2 pq = ldu2(Wq_h + n0 * 40 + ko);
                    uint2 pk = ldu2(Wk_h + n0 * 40 + ko);
                    uint2 pv = ldu2(Wv_h + n0 * 40 + ko);
                    mma16(aQ[nt], xa0[kt].x, xa1[kt].x, xa0[kt].y, xa1[kt].y, pq.x, pq.y);
                    mma16(aK[nt], xa0[kt].x, xa1[kt].x, xa0[kt].y, xa1[kt].y, pk.x, pk.y);
                    mma16(aV[nt], xa0[kt].x, xa1[kt].x, xa0[kt].y, xa1[kt].y, pv.x, pv.y);
                }
            }
            float vb[2][4];
            #pragma unroll
            for (int nt = 0; nt < 2; nt++)
                #pragma unroll
                for (int j = 0; j < 4; j++)
                    vb[nt][j] = __shfl_down_sync(0xffffffffu, aV[nt][j], 4);
            #pragma unroll
            for (int nt = 0; nt < 2; nt++) {
                int pr = nh2 * 8 + PI8(nt * 4 + t4);
                Qh[r0 * 24 + pr] = h2pack(aQ[nt][0] * QSCALE, aQ[nt][1] * QSCALE);
                Qh[r1 * 24 + pr] = h2pack(aQ[nt][2] * QSCALE, aQ[nt][3] * QSCALE);
                Kh[r0 * 24 + pr] = h2pack(aK[nt][0], aK[nt][1]);
                Kh[r1 * 24 + pr] = h2pack(aK[nt][2], aK[nt][3]);
            }
            if ((g & 1) == 0) {
                int p0 = mt8 * 8 + PI8(g >> 1);
                int p1 = mt8 * 8 + PI8(4 + (g >> 1));
                #pragma unroll
                for (int nt = 0; nt < 2; nt++) {
                    int c0 = nh2 * 16 + nt * 8 + 2 * t4;
                    Vt[(c0    ) * 72 + p0] = h2pack(aV[nt][0], vb[nt][0]);
                    Vt[(c0 + 1) * 72 + p0] = h2pack(aV[nt][1], vb[nt][1]);
                    Vt[(c0    ) * 72 + p1] = h2pack(aV[nt][2], vb[nt][2]);
                    Vt[(c0 + 1) * 72 + p1] = h2pack(aV[nt][3], vb[nt][3]);
                }
            }
        }
        bbar(bid);

        // scores in regs: M=128 N=64(own block) K=32
        float acc[4][4] = {};
        {
            const int sbase = blk * 64;
            #pragma unroll
            for (int kt = 0; kt < 2; kt++) {
                int ko = kt * 8 + 2 * t4;
                uint2 pa0 = ldu2(Qh + r0 * 24 + ko);
                uint2 pa1 = ldu2(Qh + r1 * 24 + ko);
                #pragma unroll
                for (int nt = 0; nt < 4; nt++) {
                    int s0 = sbase + nh2 * 32 + nt * 8 + g;
                    uint2 pb = ldu2(Kh + s0 * 24 + ko);
                    mma16(acc[nt], pa0.x, pa1.x, pa0.y, pa1.y, pb.x, pb.y);
                }
            }
        }
        // in-register softmax over 64 cols (pair shares rows)
        {
            float m0 = acc[0][0], m1 = acc[0][2];
            #pragma unroll
            for (int nt = 0; nt < 4; nt++) {
                m0 = fmaxf(m0, fmaxf(acc[nt][0], acc[nt][1]));
                m1 = fmaxf(m1, fmaxf(acc[nt][2], acc[nt][3]));
            }
            #pragma unroll
            for (int o = 1; o <= 2; o <<= 1) {
                m0 = fmaxf(m0, __shfl_xor_sync(0xffffffffu, m0, o));
                m1 = fmaxf(m1, __shfl_xor_sync(0xffffffffu, m1, o));
            }
            if (t4 == 0) { ExM[nh2 * 128 + r0] = m0; ExM[nh2 * 128 + r1] = m1; }
            pbar(pid);
            m0 = fmaxf(m0, ExM[(1 - nh2) * 128 + r0]);
            m1 = fmaxf(m1, ExM[(1 - nh2) * 128 + r1]);
            float s0 = 0.f, s1 = 0.f;
            #pragma unroll
            for (int nt = 0; nt < 4; nt++) {
                acc[nt][0] = __expf(acc[nt][0] - m0);
                acc[nt][1] = __expf(acc[nt][1] - m0);
                acc[nt][2] = __expf(acc[nt][2] - m1);
                acc[nt][3] = __expf(acc[nt][3] - m1);
                s0 += acc[nt][0] + acc[nt][1];
                s1 += acc[nt][2] + acc[nt][3];
            }
            #pragma unroll
            for (int o = 1; o <= 2; o <<= 1) {
                s0 += __shfl_xor_sync(0xffffffffu, s0, o);
                s1 += __shfl_xor_sync(0xffffffffu, s1, o);
            }
            if (t4 == 0) { ExS[nh2 * 128 + r0] = s0; ExS[nh2 * 128 + r1] = s1; }
            pbar(pid);
            s0 += ExS[(1 - nh2) * 128 + r0];
            s1 += ExS[(1 - nh2) * 128 + r1];
            float i0 = __frcp_rn(s0), i1 = __frcp_rn(s1);
            #pragma unroll
            for (int nt = 0; nt < 4; nt++) {
                int pp = pcperm(nh2 * 16 + nt * 4 + t4);
                Ps[r0 * 40 + pp] = h2pack(acc[nt][0] * i0, acc[nt][1] * i0);
                Ps[r1 * 40 + pp] = h2pack(acc[nt][2] * i1, acc[nt][3] * i1);
            }
        }
        pbar(pid);
        // AV: M=128 N=32 K=64(own block) -> Oh
        {
            float av[2][4] = {};
            const int kbase = blk * 32;
            #pragma unroll
            for (int kt = 0; kt < 4; kt++) {
                int ko = kt * 8 + 2 * t4;
                uint2 pa0 = ldu2(Ps + r0 * 40 + ko);
                uint2 pa1 = ldu2(Ps + r1 * 40 + ko);
                #pragma unroll
                for (int nt = 0; nt < 2; nt++) {
                    int n0 = nh2 * 16 + nt * 8 + g;
                    uint2 pb = ldu2(Vt + n0 * 72 + kbase + ko);
                    mma16(av[nt], pa0.x, pa1.x, pa0.y, pa1.y, pb.x, pb.y);
                }
            }
            #pragma unroll
            for (int nt = 0; nt < 2; nt++) {
                int pr = nh2 * 8 + PI8(nt * 4 + t4);
                Oh[r0 * 24 + pr] = h2pack(av[nt][0], av[nt][1]);
                Oh[r1 * 24 + pr] = h2pack(av[nt][2], av[nt][3]);
            }
        }
        pbar(pid);
        // out-proj partial: M=128 N=64 K=32, reg acc
        #pragma unroll
        for (int kt = 0; kt < 2; kt++) {
            int ko = kt * 8 + 2 * t4;
            uint2 pa0 = ldu2(Oh + r0 * 24 + ko);
            uint2 pa1 = ldu2(Oh + r1 * 24 + ko);
            #pragma unroll
            for (int nt = 0; nt < 4; nt++) {
                int n0 = nh2 * 32 + nt * 8 + g;
                uint2 pb = ldu2(WoS_h + n0 * 24 + ko);
                mma16(pacc[nt], pa0.x, pa1.x, pa0.y, pa1.y, pb.x, pb.y);
            }
        }
    }

    {
        int fb = r0 >> 6, t0 = r0 & 63, t1 = r1 & 63;
        int f = fp * 2 + fb;
        #pragma unroll
        for (int nt = 0; nt < 4; nt++) {
            int d0 = nh2 * 32 + nt * 8 + 2 * t4;
            float b0 = Bs[384 + d0], b1 = Bs[384 + d0 + 1];
            float2* p0 = (float2*)(out + (((size_t)(b * 64 + t0) * 128 + f) * 64 + d0));
            float2* p1 = (float2*)(out + (((size_t)(b * 64 + t1) * 128 + f) * 64 + d0));
            *p0 = make_float2(pacc[nt][0] + b0, pacc[nt][1] + b1);
            *p1 = make_float2(pacc[nt][2] + b0, pacc[nt][3] + b1);
        }
    }
}

// ---------------------------------------------------------------------------
// Feature: ONE CTA per (b,t), 128 q-rows. All-head weights staged once;
// X fragments in registers; 2 full syncs per head.
// smem words: Xs@0[128][40] Kh@5120[128][24] Vt@8192[32][72] Qh@10496[128][24]
//  Ps@13568[128][72] Oh@22784[128][24] WBall@25856(15360) WoSall@41216(6144)
//  Bs@47360(448) ExM@47808(256) ExS@48064(256)  total 48320 w = 193280 B
// ---------------------------------------------------------------------------
__global__ void __launch_bounds__(512) feature_kernel(
    const float* __restrict__ x,
    const float* __restrict__ wq, const float* __restrict__ bq,
    const float* __restrict__ wk, const float* __restrict__ bk,
    const float* __restrict__ wv, const float* __restrict__ bv,
    const float* __restrict__ wo, const float* __restrict__ bo,
    float* __restrict__ out)
{
    extern __shared__ float sm[];
    unsigned* Xs     = (unsigned*)sm;
    unsigned* Kh     = (unsigned*)sm + 5120;
    unsigned* Vt     = (unsigned*)sm + 8192;
    unsigned* Qh     = (unsigned*)sm + 10496;
    unsigned* Ps     = (unsigned*)sm + 13568;
    unsigned* Oh     = (unsigned*)sm + 22784;
    unsigned* WBall  = (unsigned*)sm + 25856;
    unsigned* WoSall = (unsigned*)sm + 41216;
    float*    Bs     = sm + 47360;
    float*    ExM    = sm + 47808;
    float*    ExS    = sm + 48064;

    const int tid  = threadIdx.x;
    const int lane = tid & 31, warp = tid >> 5;
    const int g = lane >> 2, t4 = lane & 3;
    const int b = blockIdx.x >> 6, t = blockIdx.x & 63;

    {
        const float4* x4 = (const float4*)(x + (size_t)(b * 64 + t) * 128 * 64);
        for (int i = tid; i < 2048; i += 512) {
            int row = i >> 4, c = i & 15;
            float4 v = x4[i];
            Xs[row * 40 + pcperm(2 * c)]     = h2pack(v.x, v.y);
            Xs[row * 40 + pcperm(2 * c + 1)] = h2pack(v.z, v.w);
        }
    }
    for (int i = tid; i < 12288; i += 512) {
        int mh = i >> 10;
        int m = mh >> 2, hh = mh & 3;
        int r = i & 1023;
        int n = r >> 5, p = r & 31;
        const float* w = (m == 0) ? wq : (m == 1) ? wk : wv;
        WBall[mh * 1280 + n * 40 + pcperm(p)] =
            h2pack(w[(2 * p) * 128 + hh * 32 + n],
                   w[(2 * p + 1) * 128 + hh * 32 + n]);
    }
    for (int i = tid; i < 4096; i += 512) {
        int hh = i >> 10, r = i & 1023;
        int d = r >> 4, p = r & 15;
        WoSall[hh * 1536 + d * 24 + ((p & 8) | PI8(p & 7))] =
            h2pack(wo[(hh * 32 + 2 * p) * 64 + d],
                   wo[(hh * 32 + 2 * p + 1) * 64 + d]);
    }
    if (tid < 448) {
        float v;
        if      (tid < 128) v = bq[tid];
        else if (tid < 256) v = bk[tid - 128];
        else if (tid < 384) v = bv[tid - 256];
        else                v = bo[tid - 384];
        Bs[tid] = v;
    }
    __syncthreads();

    const int mt8 = warp & 7, nh2 = warp >> 3;
    const int r0 = mt8 * 16 + g, r1 = r0 + 8;
    const int pid = 8 + mt8;

    uint2 xa0[4], xa1[4];
    #pragma unroll
    for (int kt = 0; kt < 4; kt++) {
        int ko = kt * 8 + 2 * t4;
        xa0[kt] = ldu2(Xs + r0 * 40 + ko);
        xa1[kt] = ldu2(Xs + r1 * 40 + ko);
    }

    float pacc[4][4] = {};

    for (int h = 0; h < 4; h++) {
        const int hb = h * 32;
        const unsigned* Wq_h  = WBall + h * 1280;
        const unsigned* Wk_h  = WBall + (4 + h) * 1280;
        const unsigned* Wv_h  = WBall + (8 + h) * 1280;
        const unsigned* WoS_h = WoSall + h * 1536;
        __syncthreads();   // prev head's Kh/Vt readers (CTA-wide) done

        // fused Q/K/V projections: M=128 N=32 K=64
        {
            float aQ[2][4], aK[2][4], aV[2][4];
            #pragma unroll
            for (int nt = 0; nt < 2; nt++) {
                int c0 = nh2 * 16 + nt * 8 + 2 * t4;
                aQ[nt][0] = Bs[hb + c0];       aQ[nt][1] = Bs[hb + c0 + 1];
                aQ[nt][2] = aQ[nt][0];         aQ[nt][3] = aQ[nt][1];
                aK[nt][0] = Bs[128 + hb + c0]; aK[nt][1] = Bs[128 + hb + c0 + 1];
                aK[nt][2] = aK[nt][0];         aK[nt][3] = aK[nt][1];
                aV[nt][0] = Bs[256 + hb + c0]; aV[nt][1] = Bs[256 + hb + c0 + 1];
                aV[nt][2] = aV[nt][0];         aV[nt][3] = aV[nt][1];
            }
            #pragma unroll
            for (int kt = 0; kt < 4; kt++) {
                int ko = kt * 8 + 2 * t4;
                #pragma unroll
                for (int nt = 0; nt < 2; nt++) {
                    int n0 = nh2 * 16 + nt * 8 + g;
                    uint2 pq = ldu2(Wq_h + n0 * 40 + ko);
                    uint2 pk = ldu2(Wk_h + n0 * 40 + ko);
                    uint2 pv = ldu2(Wv_h + n0 * 40 + ko);
                    mma16(aQ[nt], xa0[kt].x, xa1[kt].x, xa0[kt].y, xa1[kt].y, pq.x, pq.y);
                    mma16(aK[nt], xa0[kt].x, xa1[kt].x, xa0[kt].y, xa1[kt].y, pk.x, pk.y);
                    mma16(aV[nt], xa0[kt].x, xa1[kt].x, xa0[kt].y, xa1[kt].y, pv.x, pv.y);
                }
            }
            float vb[2][4];
            #pragma unroll
            for (int nt = 0; nt < 2; nt++)
                #pragma unroll
                for (int j = 0; j < 4; j++)
                    vb[nt][j] = __shfl_down_sync(0xffffffffu, aV[nt][j], 4);
            #pragma unroll
            for (int nt = 0; nt < 2; nt++) {
                int pr = nh2 * 8 + PI8(nt * 4 + t4);
                Qh[r0 * 24 + pr] = h2pack(aQ[nt][0] * QSCALE, aQ[nt][1] * QSCALE);
                Qh[r1 * 24 + pr] = h2pack(aQ[nt][2] * QSCALE, aQ[nt][3] * QSCALE);
                Kh[r0 * 24 + pr] = h2pack(aK[nt][0], aK[nt][1]);
                Kh[r1 * 24 + pr] = h2pack(aK[nt][2], aK[nt][3]);
            }
            if ((g & 1) == 0) {
                int p0 = mt8 * 8 + PI8(g >> 1);
                int p1 = mt8 * 8 + PI8(4 + (g >> 1));
                #pragma unroll
                for (int nt = 0; nt < 2; nt++) {
                    int c0 = nh2 * 16 + nt * 8 + 2 * t4;
                    Vt[(c0    ) * 72 + p0] = h2pack(aV[nt][0], vb[nt][0]);
                    Vt[(c0 + 1) * 72 + p0] = h2pack(aV[nt][1], vb[nt][1]);
                    Vt[(c0    ) * 72 + p1] = h2pack(aV[nt][2], vb[nt][2]);
                    Vt[(c0 + 1) * 72 + p1] = h2pack(aV[nt][3], vb[nt][3]);
                }
            }
        }
        __syncthreads();   // Kh/Vt consumed CTA-wide

        // scores in regs: M=128 N=128 K=32
        float acc[8][4] = {};
        {
            #pragma unroll
            for (int kt = 0; kt < 2; kt++) {
                int ko = kt * 8 + 2 * t4;
                uint2 pa0 = ldu2(Qh + r0 * 24 + ko);
                uint2 pa1 = ldu2(Qh + r1 * 24 + ko);
                #pragma unroll
                for (int nt = 0; nt < 8; nt++) {
                    int s0 = nh2 * 64 + nt * 8 + g;
                    uint2 pb = ldu2(Kh + s0 * 24 + ko);
                    mma16(acc[nt], pa0.x, pa1.x, pa0.y, pa1.y, pb.x, pb.y);
                }
            }
        }
        // in-register softmax over 128 cols (pair shares rows)
        {
            float m0 = acc[0][0], m1 = acc[0][2];
            #pragma unroll
            for (int nt = 0; nt < 8; nt++) {
                m0 = fmaxf(m0, fmaxf(acc[nt][0], acc[nt][1]));
                m1 = fmaxf(m1, fmaxf(acc[nt][2], acc[nt][3]));
            }
            #pragma unroll
            for (int o = 1; o <= 2; o <<= 1) {
                m0 = fmaxf(m0, __shfl_xor_sync(0xffffffffu, m0, o));
                m1 = fmaxf(m1, __shfl_xor_sync(0xffffffffu, m1, o));
            }
            if (t4 == 0) { ExM[nh2 * 128 + r0] = m0; ExM[nh2 * 128 + r1] = m1; }
            pbar(pid);
            m0 = fmaxf(m0, ExM[(1 - nh2) * 128 + r0]);
            m1 = fmaxf(m1, ExM[(1 - nh2) * 128 + r1]);
            float s0 = 0.f, s1 = 0.f;
            #pragma unroll
            for (int nt = 0; nt < 8; nt++) {
                acc[nt][0] = __expf(acc[nt][0] - m0);
                acc[nt][1] = __expf(acc[nt][1] - m0);
                acc[nt][2] = __expf(acc[nt][2] - m1);
                acc[nt][3] = __expf(acc[nt][3] - m1);
                s0 += acc[nt][0] + acc[nt][1];
                s1 += acc[nt][2] + acc[nt][3];
            }
            #pragma unroll
            for (int o = 1; o <= 2; o <<= 1) {
                s0 += __shfl_xor_sync(0xffffffffu, s0, o);
                s1 += __shfl_xor_sync(0xffffffffu, s1, o);
            }
            if (t4 == 0) { ExS[nh2 * 128 + r0] = s0; ExS[nh2 * 128 + r1] = s1; }
            pbar(pid);
            s0 += ExS[(1 - nh2) * 128 + r0];
            s1 += ExS[(1 - nh2) * 128 + r1];
            float i0 = __frcp_rn(s0), i1 = __frcp_rn(s1);
            #pragma unroll
            for (int nt = 0; nt < 8; nt++) {
                int pp = pcperm(nh2 * 32 + nt * 4 + t4);
                Ps[r0 * 72 + pp] = h2pack(acc[nt][0] * i0, acc[nt][1] * i0);
                Ps[r1 * 72 + pp] = h2pack(acc[nt][2] * i1, acc[nt][3] * i1);
            }
        }
        pbar(pid);
        // AV: M=128 N=32 K=128 -> Oh
        {
            float av[2][4] = {};
            #pragma unroll
            for (int kt = 0; kt < 8; kt++) {
                int ko = kt * 8 + 2 * t4;
                uint2 pa0 = ldu2(Ps + r0 * 72 + ko);
                uint2 pa1 = ldu2(Ps + r1 * 72 + ko);
                #pragma unroll
                for (int nt = 0; nt < 2; nt++) {
                    int n0 = nh2 * 16 + nt * 8 + g;
                    uint2 pb = ldu2(Vt + n0 * 72 + ko);
                    mma16(av[nt], pa0.x, pa1.x, pa0.y, pa1.y, pb.x, pb.y);
                }
            }
            #pragma unroll
            for (int nt = 0; nt < 2; nt++) {
                int pr = nh2 * 8 + PI8(nt * 4 + t4);
                Oh[r0 * 24 + pr] = h2pack(av[nt][0], av[nt][1]);
                Oh[r1 * 24 + pr] = h2pack(av[nt][2], av[nt][3]);
            }
        }
        pbar(pid);
        // out-proj partial: M=128 N=64 K=32, reg acc
        #pragma unroll
        for (int kt = 0; kt < 2; kt++) {
            int ko = kt * 8 + 2 * t4;
            uint2 pa0 = ldu2(Oh + r0 * 24 + ko);
            uint2 pa1 = ldu2(Oh + r1 * 24 + ko);
            #pragma unroll
            for (int nt = 0; nt < 4; nt++) {
                int n0 = nh2 * 32 + nt * 8 + g;
                uint2 pb = ldu2(WoS_h + n0 * 24 + ko);
                mma16(pacc[nt], pa0.x, pa1.x, pa0.y, pa1.y, pb.x, pb.y);
            }
        }
    }

    #pragma unroll
    for (int nt = 0; nt < 4; nt++) {
        int d0 = nh2 * 32 + nt * 8 + 2 * t4;
        float b0 = Bs[384 + d0], b1 = Bs[384 + d0 + 1];
        float2* p0 = (float2*)(out + (((size_t)(b * 64 + t) * 128 + r0) * 64 + d0));
        float2* p1 = (float2*)(out + (((size_t)(b * 64 + t) * 128 + r1) * 64 + d0));
        float2 v0 = *p0, v1 = *p1;
        v0.x += pacc[nt][0] + b0; v0.y += pacc[nt][1] + b1;
        v1.x += pacc[nt][2] + b0; v1.y += pacc[nt][3] + b1;
        *p0 = v0; *p1 = v1;
    }
}

// ---------------------------------------------------------------------------
extern "C" void kernel_launch(void* const* d_in, const int* in_sizes, int n_in,
                              void* d_out, int out_size)
{
    const float* x = (const float*)d_in[0];
    const float *tqw, *tqb, *tkw, *tkb, *tvw, *tvb, *tow, *tob;
    const float *fqw, *fqb, *fkw, *fkb, *fvw, *fvb, *fow, *fob;

    if (in_sizes[8] == 64) {   // reference-signature order
        tqw = (const float*)d_in[1];  tqb = (const float*)d_in[2];
        tkw = (const float*)d_in[3];  tkb = (const float*)d_in[4];
        tvw = (const float*)d_in[5];  tvb = (const float*)d_in[6];
        tow = (const float*)d_in[7];  tob = (const float*)d_in[8];
        fqw = (const float*)d_in[9];  fqb = (const float*)d_in[10];
        fkw = (const float*)d_in[11]; fkb = (const float*)d_in[12];
        fvw = (const float*)d_in[13]; fvb = (const float*)d_in[14];
        fow = (const float*)d_in[15]; fob = (const float*)d_in[16];
    } else {                    // setup_inputs dict order
        tqw = (const float*)d_in[1];  tqb = (const float*)d_in[2];
        tkw = (const float*)d_in[3];  tkb = (const float*)d_in[4];
        tvw = (const float*)d_in[5];  tvb = (const float*)d_in[6];
        fqw = (const float*)d_in[7];  fqb = (const float*)d_in[8];
        fkw = (const float*)d_in[9];  fkb = (const float*)d_in[10];
        fvw = (const float*)d_in[11]; fvb = (const float*)d_in[12];
        tow = (const float*)d_in[13]; tob = (const float*)d_in[14];
        fow = (const float*)d_in[15]; fob = (const float*)d_in[16];
    }

    float* out = (float*)d_out;

    const size_t sm_t = 44224 * sizeof(float);   // 176896 B
    const size_t sm_f = 48320 * sizeof(float);   // 193280 B

    cudaFuncSetAttribute(temporal_kernel,
                         cudaFuncAttributeMaxDynamicSharedMemorySize, (int)sm_t);
    cudaFuncSetAttribute(feature_kernel,
                         cudaFuncAttributeMaxDynamicSharedMemorySize, (int)sm_f);

    temporal_kernel<<<32 * 64, 512, sm_t>>>(x, tqw, tqb, tkw, tkb, tvw, tvb,
                                            tow, tob, out);
    feature_kernel<<<32 * 64, 512, sm_f>>>(x, fqw, fqb, fkw, fkb, fvw, fvb,
                                           fow, fob, out);
}